// round 1
// baseline (speedup 1.0000x reference)
#include <cuda_runtime.h>
#include <cuda_bf16.h>
#include <math.h>

// PointTransformerLayer: B=1, N=1024, D=64, H_POS=64, H_ATTN=256
//
// Math restructuring:
//   pp[i]  = pos[i] @ pW1                       (precomputed, linear)
//   h_ij   = relu(pp_i - pp_j + pb1)            (elementwise)
//   rpe_ij = h_ij @ pW2 + pb2
//   g_ij   = q_i - k_j + rpe_ij                 (q,k,v precomputed)
//   u_ij   = relu(g_ij @ aW1 + ab1)
//   sim_ij = u_ij @ aW2            (+ab2 dropped: constant over j, softmax-invariant)
//   attn   = online softmax over j, per channel d
//   out[i,d] = sum_j attn_ijd * (v[j,d] + rpe_ijd)

#define NN 1024
#define DD 64

__device__ float g_q[NN * DD];
__device__ float g_k[NN * DD];
__device__ float g_v[NN * DD];
__device__ float g_pp[NN * DD];

// ---------------------------------------------------------------------------
// Precompute: q = x@Wq, k = x@Wk, v = x@Wv, pp = pos@pW1
// ---------------------------------------------------------------------------
__global__ void pt_precompute(const float* __restrict__ x,
                              const float* __restrict__ pos,
                              const float* __restrict__ Wq,
                              const float* __restrict__ Wk,
                              const float* __restrict__ Wv,
                              const float* __restrict__ pW1)
{
    const int i = blockIdx.x;
    const int d = threadIdx.x;  // 64 threads
    __shared__ float xr[DD];
    xr[d] = x[i * DD + d];
    __syncthreads();
    float aq = 0.f, ak = 0.f, av = 0.f;
    #pragma unroll 8
    for (int m = 0; m < DD; ++m) {
        float xv = xr[m];
        aq = fmaf(xv, Wq[m * DD + d], aq);
        ak = fmaf(xv, Wk[m * DD + d], ak);
        av = fmaf(xv, Wv[m * DD + d], av);
    }
    g_q[i * DD + d] = aq;
    g_k[i * DD + d] = ak;
    g_v[i * DD + d] = av;
    g_pp[i * DD + d] = pos[i * 2 + 0] * pW1[d] + pos[i * 2 + 1] * pW1[DD + d];
}

// ---------------------------------------------------------------------------
// Main kernel: one CTA per query i, 256 threads, j tiled by 64.
// Shared memory layout (float offsets):
// ---------------------------------------------------------------------------
#define OFF_AW1T 0                        // aW1 transposed: [c=256][m=64] stride 68 (16B-aligned rows)
#define OFF_AW2  (OFF_AW1T + 256 * 68)   // aW2 [c=256][d=64]
#define OFF_PW2  (OFF_AW2 + 256 * 64)    // pW2 [m=64][d=64]
#define OFF_R    (OFF_PW2 + 64 * 64)     // rpe tile [j=64][d=64] stride 65 (bank-conflict-free cols)
#define OFF_SIM  (OFF_R + 64 * 65)       // sim tile [j=64][d=64] stride 65
#define OFF_RED  (OFF_SIM + 64 * 65)     // 4x64 reduction scratch
#define OFF_RED2 (OFF_RED + 256)         // 4x64 reduction scratch
#define OFF_PPI  (OFF_RED2 + 256)        // pp[i] (64)
#define OFF_QI   (OFF_PPI + 64)          // q[i]  (64)
#define OFF_PB1  (OFF_QI + 64)
#define OFF_PB2  (OFF_PB1 + 64)
#define OFF_AB1  (OFF_PB2 + 64)          // 256
#define SMEM_FLOATS (OFF_AB1 + 256)      // 47232 floats = 188928 bytes

__global__ __launch_bounds__(256, 1) void pt_main(
    const float* __restrict__ pW2g, const float* __restrict__ pb1g,
    const float* __restrict__ pb2g, const float* __restrict__ aW1g,
    const float* __restrict__ ab1g, const float* __restrict__ aW2g,
    float* __restrict__ out)
{
    extern __shared__ float sm[];
    const int tid = threadIdx.x;
    const int i = blockIdx.x;

    // ---- cooperative weight/bias loads (all L2-resident, ~150KB) ----
    for (int idx = tid; idx < 64 * 256; idx += 256) {
        int m = idx >> 8, c = idx & 255;               // aW1 is [m][c]
        sm[OFF_AW1T + c * 68 + m] = aW1g[idx];         // store transposed [c][m]
    }
    for (int idx = tid; idx < 256 * 64; idx += 256) sm[OFF_AW2 + idx] = aW2g[idx];
    for (int idx = tid; idx < 64 * 64; idx += 256)  sm[OFF_PW2 + idx] = pW2g[idx];
    if (tid < 64) {
        sm[OFF_PPI + tid] = g_pp[i * 64 + tid];
        sm[OFF_QI + tid]  = g_q[i * 64 + tid];
        sm[OFF_PB1 + tid] = pb1g[tid];
        sm[OFF_PB2 + tid] = pb2g[tid];
    }
    sm[OFF_AB1 + tid] = ab1g[tid];
    __syncthreads();

    const int j  = tid & 63;   // j-lane within tile (also channel d in softmax phase)
    const int cg = tid >> 6;   // group 0..3 (c-range in MLP phase, j-range in softmax phase)

    float m_run = -1e30f, s_run = 0.f, a_run = 0.f;  // online-softmax state (channel j)

    for (int jt = 0; jt < 16; ++jt) {
        const int j0 = jt << 6;

        // ---- Phase B: h on the fly, rpe partial. Thread computes R[j][cg*16 .. +15]
        {
            float r[16];
            #pragma unroll
            for (int t = 0; t < 16; ++t) r[t] = sm[OFF_PB2 + cg * 16 + t];
            const float4* pp4 = reinterpret_cast<const float4*>(g_pp + (j0 + j) * 64);
            #pragma unroll 4
            for (int m4 = 0; m4 < 16; ++m4) {
                float4 p = pp4[m4];
                float h0 = fmaxf(sm[OFF_PPI + 4 * m4 + 0] - p.x + sm[OFF_PB1 + 4 * m4 + 0], 0.f);
                float h1 = fmaxf(sm[OFF_PPI + 4 * m4 + 1] - p.y + sm[OFF_PB1 + 4 * m4 + 1], 0.f);
                float h2 = fmaxf(sm[OFF_PPI + 4 * m4 + 2] - p.z + sm[OFF_PB1 + 4 * m4 + 2], 0.f);
                float h3 = fmaxf(sm[OFF_PPI + 4 * m4 + 3] - p.w + sm[OFF_PB1 + 4 * m4 + 3], 0.f);
                const float4* w0 = reinterpret_cast<const float4*>(sm + OFF_PW2 + (4 * m4 + 0) * 64 + cg * 16);
                const float4* w1 = reinterpret_cast<const float4*>(sm + OFF_PW2 + (4 * m4 + 1) * 64 + cg * 16);
                const float4* w2 = reinterpret_cast<const float4*>(sm + OFF_PW2 + (4 * m4 + 2) * 64 + cg * 16);
                const float4* w3 = reinterpret_cast<const float4*>(sm + OFF_PW2 + (4 * m4 + 3) * 64 + cg * 16);
                #pragma unroll
                for (int q4 = 0; q4 < 4; ++q4) {
                    float4 a = w0[q4], b = w1[q4], c2 = w2[q4], d2 = w3[q4];
                    r[4 * q4 + 0] = fmaf(h3, d2.x, fmaf(h2, c2.x, fmaf(h1, b.x, fmaf(h0, a.x, r[4 * q4 + 0]))));
                    r[4 * q4 + 1] = fmaf(h3, d2.y, fmaf(h2, c2.y, fmaf(h1, b.y, fmaf(h0, a.y, r[4 * q4 + 1]))));
                    r[4 * q4 + 2] = fmaf(h3, d2.z, fmaf(h2, c2.z, fmaf(h1, b.z, fmaf(h0, a.z, r[4 * q4 + 2]))));
                    r[4 * q4 + 3] = fmaf(h3, d2.w, fmaf(h2, c2.w, fmaf(h1, b.w, fmaf(h0, a.w, r[4 * q4 + 3]))));
                }
            }
            #pragma unroll
            for (int t = 0; t < 16; ++t) sm[OFF_R + j * 65 + cg * 16 + t] = r[t];
        }
        __syncthreads();

        // ---- Phase C: g = q_i - k_j + rpe (register-resident, same for all cg of a j)
        float greg[64];
        {
            const float4* k4 = reinterpret_cast<const float4*>(g_k + (j0 + j) * 64);
            #pragma unroll
            for (int m4 = 0; m4 < 16; ++m4) {
                float4 kv = k4[m4];
                greg[4 * m4 + 0] = sm[OFF_QI + 4 * m4 + 0] - kv.x + sm[OFF_R + j * 65 + 4 * m4 + 0];
                greg[4 * m4 + 1] = sm[OFF_QI + 4 * m4 + 1] - kv.y + sm[OFF_R + j * 65 + 4 * m4 + 1];
                greg[4 * m4 + 2] = sm[OFF_QI + 4 * m4 + 2] - kv.z + sm[OFF_R + j * 65 + 4 * m4 + 2];
                greg[4 * m4 + 3] = sm[OFF_QI + 4 * m4 + 3] - kv.w + sm[OFF_R + j * 65 + 4 * m4 + 3];
            }
        }

        // ---- Phase D: u = relu(g@aW1+ab1) over this cg's 64 c's; sim partial = u@aW2
        float simreg[64];
        #pragma unroll
        for (int t = 0; t < 64; ++t) simreg[t] = 0.f;
        #pragma unroll 2
        for (int cc = 0; cc < 64; ++cc) {
            const int c = (cg << 6) + cc;
            const float4* w4 = reinterpret_cast<const float4*>(sm + OFF_AW1T + c * 68);
            float u0 = 0.f, u1 = 0.f, u2 = 0.f, u3 = 0.f;
            #pragma unroll
            for (int m4 = 0; m4 < 16; ++m4) {
                float4 w = w4[m4];
                u0 = fmaf(greg[4 * m4 + 0], w.x, u0);
                u1 = fmaf(greg[4 * m4 + 1], w.y, u1);
                u2 = fmaf(greg[4 * m4 + 2], w.z, u2);
                u3 = fmaf(greg[4 * m4 + 3], w.w, u3);
            }
            float u = fmaxf((u0 + u1) + (u2 + u3) + sm[OFF_AB1 + c], 0.f);
            const float4* a4 = reinterpret_cast<const float4*>(sm + OFF_AW2 + c * 64);
            #pragma unroll
            for (int d4 = 0; d4 < 16; ++d4) {
                float4 a = a4[d4];
                simreg[4 * d4 + 0] = fmaf(u, a.x, simreg[4 * d4 + 0]);
                simreg[4 * d4 + 1] = fmaf(u, a.y, simreg[4 * d4 + 1]);
                simreg[4 * d4 + 2] = fmaf(u, a.z, simreg[4 * d4 + 2]);
                simreg[4 * d4 + 3] = fmaf(u, a.w, simreg[4 * d4 + 3]);
            }
        }

        // ---- sim reduction across the 4 cg groups (sequential, 4 steps)
        if (cg == 0) {
            #pragma unroll
            for (int t = 0; t < 64; ++t) sm[OFF_SIM + j * 65 + t] = simreg[t];
        }
        __syncthreads();
        if (cg == 1) {
            #pragma unroll
            for (int t = 0; t < 64; ++t) sm[OFF_SIM + j * 65 + t] += simreg[t];
        }
        __syncthreads();
        if (cg == 2) {
            #pragma unroll
            for (int t = 0; t < 64; ++t) sm[OFF_SIM + j * 65 + t] += simreg[t];
        }
        __syncthreads();
        if (cg == 3) {
            #pragma unroll
            for (int t = 0; t < 64; ++t) sm[OFF_SIM + j * 65 + t] += simreg[t];
        }
        __syncthreads();

        // ---- Phase E: online softmax update. Roles: channel d = j, j-range = cg.
        {
            float lmax = -1e30f;
            #pragma unroll
            for (int t = 0; t < 16; ++t)
                lmax = fmaxf(lmax, sm[OFF_SIM + (cg * 16 + t) * 65 + j]);
            sm[OFF_RED + cg * 64 + j] = lmax;
            __syncthreads();
            float tmax = fmaxf(fmaxf(sm[OFF_RED + j], sm[OFF_RED + 64 + j]),
                               fmaxf(sm[OFF_RED + 128 + j], sm[OFF_RED + 192 + j]));
            float m_new = fmaxf(m_run, tmax);
            float corr = __expf(m_run - m_new);
            float ps = 0.f, pa = 0.f;
            #pragma unroll
            for (int t = 0; t < 16; ++t) {
                int jj = cg * 16 + t;
                float e = __expf(sm[OFF_SIM + jj * 65 + j] - m_new);
                ps += e;
                pa = fmaf(e, g_v[(j0 + jj) * 64 + j] + sm[OFF_R + jj * 65 + j], pa);
            }
            __syncthreads();  // red buffers reused
            sm[OFF_RED + cg * 64 + j] = ps;
            sm[OFF_RED2 + cg * 64 + j] = pa;
            __syncthreads();
            float S = sm[OFF_RED + j] + sm[OFF_RED + 64 + j] +
                      sm[OFF_RED + 128 + j] + sm[OFF_RED + 192 + j];
            float A = sm[OFF_RED2 + j] + sm[OFF_RED2 + 64 + j] +
                      sm[OFF_RED2 + 128 + j] + sm[OFF_RED2 + 192 + j];
            s_run = s_run * corr + S;
            a_run = a_run * corr + A;
            m_run = m_new;
        }
    }

    if (cg == 0) out[i * 64 + j] = a_run / s_run;
}

// ---------------------------------------------------------------------------
extern "C" void kernel_launch(void* const* d_in, const int* in_sizes, int n_in,
                              void* d_out, int out_size)
{
    const float* x   = (const float*)d_in[0];
    const float* pos = (const float*)d_in[1];
    const float* Wq  = (const float*)d_in[2];
    const float* Wk  = (const float*)d_in[3];
    const float* Wv  = (const float*)d_in[4];
    const float* pW1 = (const float*)d_in[5];
    const float* pb1 = (const float*)d_in[6];
    const float* pW2 = (const float*)d_in[7];
    const float* pb2 = (const float*)d_in[8];
    const float* aW1 = (const float*)d_in[9];
    const float* ab1 = (const float*)d_in[10];
    const float* aW2 = (const float*)d_in[11];
    // d_in[12] = ab2: constant over j, cancels in the per-channel softmax -> unused.
    float* out = (float*)d_out;

    (void)in_sizes; (void)n_in; (void)out_size;

    cudaFuncSetAttribute(pt_main, cudaFuncAttributeMaxDynamicSharedMemorySize,
                         SMEM_FLOATS * (int)sizeof(float));

    pt_precompute<<<NN, DD>>>(x, pos, Wq, Wk, Wv, pW1);
    pt_main<<<NN, 256, SMEM_FLOATS * sizeof(float)>>>(pW2, pb1, pb2, aW1, ab1, aW2, out);
}